// round 2
// baseline (speedup 1.0000x reference)
#include <cuda_runtime.h>
#include <cstdint>

// Problem constants
constexpr int Bsz = 4;
constexpr int Sq  = 2048;
constexpr int Dm  = 1024;

// Scratch (device globals: no allocation allowed)
__device__ float g_X [(long)Bsz * Sq * Dm];   // tf32-rounded x
__device__ float g_Wq[(long)Dm * Dm];
__device__ float g_Wk[(long)Dm * Dm];
__device__ float g_Wv[(long)Dm * Dm];
__device__ float g_Q [(long)Bsz * Sq * Dm];
__device__ float g_K [(long)Bsz * Sq * Dm];
__device__ float g_V [(long)Bsz * Sq * Dm];
__device__ float g_P [(long)Bsz * Sq * Sq];   // scores -> probabilities

// ---------------------------------------------------------------------------
// helpers
// ---------------------------------------------------------------------------
__device__ __forceinline__ void cp_async16(void* smem, const void* gmem) {
    uint32_t s = (uint32_t)__cvta_generic_to_shared(smem);
    asm volatile("cp.async.cg.shared.global [%0], [%1], 16;\n" :: "r"(s), "l"(gmem));
}
__device__ __forceinline__ void cp_commit() { asm volatile("cp.async.commit_group;\n"); }
__device__ __forceinline__ void cp_wait1()  { asm volatile("cp.async.wait_group 1;\n"); }
__device__ __forceinline__ void cp_wait0()  { asm volatile("cp.async.wait_group 0;\n"); }

__device__ __forceinline__ uint32_t f2tf32(float f) {
    uint32_t r;
    asm("cvt.rna.tf32.f32 %0, %1;" : "=r"(r) : "f"(f));
    return r;
}

__device__ __forceinline__ void mma_tf32(float* d, const uint32_t* a, const uint32_t* b) {
    asm volatile(
        "mma.sync.aligned.m16n8k8.row.col.f32.tf32.tf32.f32 "
        "{%0,%1,%2,%3},{%4,%5,%6,%7},{%8,%9},{%0,%1,%2,%3};"
        : "+f"(d[0]), "+f"(d[1]), "+f"(d[2]), "+f"(d[3])
        : "r"(a[0]), "r"(a[1]), "r"(a[2]), "r"(a[3]), "r"(b[0]), "r"(b[1]));
}

__device__ __forceinline__ float warp_max(float v) {
    #pragma unroll
    for (int o = 16; o; o >>= 1) v = fmaxf(v, __shfl_xor_sync(0xFFFFFFFFu, v, o));
    return v;
}
__device__ __forceinline__ float warp_sum(float v) {
    #pragma unroll
    for (int o = 16; o; o >>= 1) v += __shfl_xor_sync(0xFFFFFFFFu, v, o);
    return v;
}

// ---------------------------------------------------------------------------
// Pre-round a buffer to tf32-representable floats (cvt.rna once per value).
// ---------------------------------------------------------------------------
__global__ void __launch_bounds__(256)
round_k(const float* __restrict__ in, float* __restrict__ out, int n4)
{
    int i = blockIdx.x * blockDim.x + threadIdx.x;
    int stride = gridDim.x * blockDim.x;
    for (; i < n4; i += stride) {
        float4 v = ((const float4*)in)[i];
        v.x = __uint_as_float(f2tf32(v.x));
        v.y = __uint_as_float(f2tf32(v.y));
        v.z = __uint_as_float(f2tf32(v.z));
        v.w = __uint_as_float(f2tf32(v.w));
        ((float4*)out)[i] = v;
    }
}

// ---------------------------------------------------------------------------
// TF32 tensor-core GEMM, 128x128x16 CTA tile, 256 threads (8 warps, 2x4).
// Warp tile 64x32 = 4x4 m16n8k8.  Operands are PRE-ROUNDED tf32 values in
// gmem, so the inner loop has zero cvt instructions.
// TRANS_B:     B is [N,K] row-major (scores: Q @ K^T)
// CAUSAL_SKIP: skip CTAs fully above the diagonal (scores)
// KLIMIT:      K-loop limit = m0+128 (PV GEMM, causal)
// ROUND_OUT:   round outputs to tf32 (intermediates consumed by later mmas)
// ---------------------------------------------------------------------------
template <bool TRANS_B, bool CAUSAL_SKIP, bool KLIMIT, bool ROUND_OUT>
__global__ void __launch_bounds__(256, 2)
gemm_k(const float* __restrict__ A, const float* __restrict__ Bm,
       float* __restrict__ C,
       int K, int lda, int ldb, int ldc,
       long sA, long sB, long sC)
{
    const int m0 = blockIdx.y * 128;
    const int n0 = blockIdx.x * 128;
    if (CAUSAL_SKIP && n0 > m0 + 127) return;

    A  += (long)blockIdx.z * sA;
    Bm += (long)blockIdx.z * sB;
    C  += (long)blockIdx.z * sC;

    int Keff = K;
    if (KLIMIT) Keff = min(K, m0 + 128);
    const int nkt = Keff >> 4;   // K / 16

    constexpr int BROWS = TRANS_B ? 128 : 16;
    constexpr int BLD   = TRANS_B ? 20  : 132;

    __shared__ __align__(16) float As[2][128][20];
    __shared__ __align__(16) float Bs[2][BROWS][BLD];

    const int tid  = threadIdx.x;
    const int warp = tid >> 5;
    const int lane = tid & 31;
    const int wm   = warp >> 2;   // 0..1  -> 64 rows each
    const int wn   = warp & 3;    // 0..3  -> 32 cols each

    auto load_stage = [&](int st, int kt) {
        const int k0 = kt << 4;
        // A: 128x16 = 512 float4, 2 per thread
        #pragma unroll
        for (int i = 0; i < 2; i++) {
            int idx = tid + 256 * i;
            int r = idx >> 2, c = (idx & 3) * 4;
            cp_async16(&As[st][r][c], A + (long)(m0 + r) * lda + k0 + c);
        }
        if (TRANS_B) {
            #pragma unroll
            for (int i = 0; i < 2; i++) {
                int idx = tid + 256 * i;
                int r = idx >> 2, c = (idx & 3) * 4;
                cp_async16(&Bs[st][r][c], Bm + (long)(n0 + r) * ldb + k0 + c);
            }
        } else {
            #pragma unroll
            for (int i = 0; i < 2; i++) {
                int idx = tid + 256 * i;
                int r = idx >> 5, c = (idx & 31) * 4;
                cp_async16(&Bs[st][r][c], Bm + (long)(k0 + r) * ldb + n0 + c);
            }
        }
        cp_commit();
    };

    float acc[4][4][4] = {};

    load_stage(0, 0);
    for (int kt = 0; kt < nkt; ++kt) {
        const int cur = kt & 1;
        if (kt + 1 < nkt) { load_stage(cur ^ 1, kt + 1); cp_wait1(); }
        else              { cp_wait0(); }
        __syncthreads();

        #pragma unroll
        for (int kk = 0; kk < 16; kk += 8) {
            uint32_t af[4][4], bf[4][2];
            #pragma unroll
            for (int mi = 0; mi < 4; mi++) {
                const int rb = wm * 64 + mi * 16 + (lane >> 2);
                const int cb = kk + (lane & 3);
                af[mi][0] = __float_as_uint(As[cur][rb][cb]);
                af[mi][1] = __float_as_uint(As[cur][rb + 8][cb]);
                af[mi][2] = __float_as_uint(As[cur][rb][cb + 4]);
                af[mi][3] = __float_as_uint(As[cur][rb + 8][cb + 4]);
            }
            #pragma unroll
            for (int ni = 0; ni < 4; ni++) {
                const int nb = wn * 32 + ni * 8 + (lane >> 2);
                if (TRANS_B) {
                    bf[ni][0] = __float_as_uint(Bs[cur][nb][kk + (lane & 3)]);
                    bf[ni][1] = __float_as_uint(Bs[cur][nb][kk + (lane & 3) + 4]);
                } else {
                    bf[ni][0] = __float_as_uint(Bs[cur][kk + (lane & 3)][nb]);
                    bf[ni][1] = __float_as_uint(Bs[cur][kk + (lane & 3) + 4][nb]);
                }
            }
            #pragma unroll
            for (int mi = 0; mi < 4; mi++)
                #pragma unroll
                for (int ni = 0; ni < 4; ni++)
                    mma_tf32(acc[mi][ni], af[mi], bf[ni]);
        }
        __syncthreads();
    }

    // Epilogue
    #pragma unroll
    for (int mi = 0; mi < 4; mi++) {
        #pragma unroll
        for (int ni = 0; ni < 4; ni++) {
            const int r0 = m0 + wm * 64 + mi * 16 + (lane >> 2);
            const int c0 = n0 + wn * 32 + ni * 8 + 2 * (lane & 3);
            float4 v = make_float4(acc[mi][ni][0], acc[mi][ni][1],
                                   acc[mi][ni][2], acc[mi][ni][3]);
            if (ROUND_OUT) {
                v.x = __uint_as_float(f2tf32(v.x));
                v.y = __uint_as_float(f2tf32(v.y));
                v.z = __uint_as_float(f2tf32(v.z));
                v.w = __uint_as_float(f2tf32(v.w));
            }
            *(float2*)&C[(long)r0 * ldc + c0]       = make_float2(v.x, v.y);
            *(float2*)&C[(long)(r0 + 8) * ldc + c0] = make_float2(v.z, v.w);
        }
    }
}

// ---------------------------------------------------------------------------
// In-place causal row softmax, logits s/32.  Writes probabilities rounded to
// tf32 (they feed the PV mma).  Zero-fills only up to the next 128 boundary
// (the PV GEMM's causal K-limit never reads past that).
// ---------------------------------------------------------------------------
__global__ void __launch_bounds__(256)
softmax_k(float* __restrict__ P)
{
    const int row = blockIdx.x;        // 0 .. Bsz*Sq-1
    const int b = row >> 11;
    const int i = row & 2047;
    float* p = P + ((long)b * Sq + i) * Sq;
    const int tid = threadIdx.x;
    const int len = i + 1;
    const int lenPad = (len + 127) & ~127;   // PV reads k < lenPad only

    float v[8];
    int cnt = 0;
    for (int j = tid; j < len; j += 256) v[cnt++] = p[j];

    float mx = -3.4e38f;
    #pragma unroll
    for (int c = 0; c < 8; c++) if (c < cnt) mx = fmaxf(mx, v[c]);
    mx = warp_max(mx);

    __shared__ float red[8];
    if ((tid & 31) == 0) red[tid >> 5] = mx;
    __syncthreads();
    mx = red[0];
    #pragma unroll
    for (int w = 1; w < 8; w++) mx = fmaxf(mx, red[w]);

    float s = 0.f;
    #pragma unroll
    for (int c = 0; c < 8; c++) {
        if (c < cnt) { v[c] = __expf((v[c] - mx) * 0.03125f); s += v[c]; }
    }
    s = warp_sum(s);
    __syncthreads();
    if ((tid & 31) == 0) red[tid >> 5] = s;
    __syncthreads();
    float tot = 0.f;
    #pragma unroll
    for (int w = 0; w < 8; w++) tot += red[w];
    const float inv = 1.0f / tot;

    cnt = 0;
    for (int j = tid; j < lenPad; j += 256) {
        float val = (j < len) ? v[cnt++] * inv : 0.0f;
        p[j] = __uint_as_float(f2tf32(val));
    }
}

// ---------------------------------------------------------------------------
extern "C" void kernel_launch(void* const* d_in, const int* in_sizes, int n_in,
                              void* d_out, int out_size)
{
    const float* x  = (const float*)d_in[0];
    const float* Wq = (const float*)d_in[1];
    const float* Wk = (const float*)d_in[2];
    const float* Wv = (const float*)d_in[3];
    float* out = (float*)d_out;

    float *X, *RWq, *RWk, *RWv, *Q, *K, *V, *P;
    cudaGetSymbolAddress((void**)&X,   g_X);
    cudaGetSymbolAddress((void**)&RWq, g_Wq);
    cudaGetSymbolAddress((void**)&RWk, g_Wk);
    cudaGetSymbolAddress((void**)&RWv, g_Wv);
    cudaGetSymbolAddress((void**)&Q,   g_Q);
    cudaGetSymbolAddress((void**)&K,   g_K);
    cudaGetSymbolAddress((void**)&V,   g_V);
    cudaGetSymbolAddress((void**)&P,   g_P);

    const dim3 blk(256);
    const int M = Bsz * Sq;   // 8192

    // 0) Pre-round operands to tf32 values (removes all cvt from GEMM loops)
    round_k<<<512, 256>>>(x,  X,   (Bsz * Sq * Dm) / 4);
    round_k<<<128, 256>>>(Wq, RWq, (Dm * Dm) / 4);
    round_k<<<128, 256>>>(Wk, RWk, (Dm * Dm) / 4);
    round_k<<<128, 256>>>(Wv, RWv, (Dm * Dm) / 4);

    // 1) Projections (NN), outputs rounded to tf32
    {
        dim3 grid(Dm / 128, M / 128, 1);
        gemm_k<false, false, false, true><<<grid, blk>>>(X, RWq, Q, Dm, Dm, Dm, Dm, 0, 0, 0);
        gemm_k<false, false, false, true><<<grid, blk>>>(X, RWk, K, Dm, Dm, Dm, Dm, 0, 0, 0);
        gemm_k<false, false, false, true><<<grid, blk>>>(X, RWv, V, Dm, Dm, Dm, Dm, 0, 0, 0);
    }

    // 2) Scores: S_b = Q_b K_b^T  (NT, causal-skip)
    {
        dim3 grid(Sq / 128, Sq / 128, Bsz);
        gemm_k<true, true, false, false><<<grid, blk>>>(
            Q, K, P, Dm, Dm, Dm, Sq,
            (long)Sq * Dm, (long)Sq * Dm, (long)Sq * Sq);
    }

    // 3) Softmax (in place, causal, scale 1/32, tf32-rounded output)
    softmax_k<<<Bsz * Sq, 256>>>(P);

    // 4) O = P V  (NN, causal K-limit), full-precision output
    {
        dim3 grid(Dm / 128, Sq / 128, Bsz);
        gemm_k<false, false, true, false><<<grid, blk>>>(
            P, V, out, Sq, Sq, Dm, Dm,
            (long)Sq * Sq, (long)Sq * Dm, (long)Sq * Dm);
    }

    (void)in_sizes; (void)n_in; (void)out_size;
}

// round 4
// speedup vs baseline: 1.0703x; 1.0703x over previous
#include <cuda_runtime.h>
#include <cstdint>

// Problem constants
constexpr int Bsz = 4;
constexpr int Sq  = 2048;
constexpr int Dm  = 1024;

// Scratch (device globals; no allocation allowed)
__device__ float g_X  [(long)Bsz * Sq * Dm];   // tf32-rounded, perm-K layout
__device__ float g_WqT[(long)Dm * Dm];         // rounded + transposed + perm-K
__device__ float g_WkT[(long)Dm * Dm];
__device__ float g_WvT[(long)Dm * Dm];
__device__ float g_Q  [(long)Bsz * Sq * Dm];   // perm-K
__device__ float g_K  [(long)Bsz * Sq * Dm];   // perm-K
__device__ float g_V  [(long)Bsz * Sq * Dm];   // normal
__device__ float g_Vt [(long)Bsz * Sq * Dm];   // V^T per batch, perm-K
__device__ float g_P  [(long)Bsz * Sq * Sq];   // scores->probs, perm-K

// ---------------------------------------------------------------------------
// helpers
// ---------------------------------------------------------------------------
__device__ __forceinline__ uint32_t f2tf32(float f) {
    uint32_t r;
    asm("cvt.rna.tf32.f32 %0, %1;" : "=r"(r) : "f"(f));
    return r;
}
__device__ __forceinline__ float roundtf(float f) { return __uint_as_float(f2tf32(f)); }

__device__ __forceinline__ void cp16(void* s, const void* g) {
    uint32_t sa = (uint32_t)__cvta_generic_to_shared(s);
    asm volatile("cp.async.cg.shared.global [%0], [%1], 16;\n" :: "r"(sa), "l"(g));
}

__device__ __forceinline__ void mma_tf32(float* d, const float4& alo, const float4& ahi,
                                         float bx, float by) {
    asm volatile(
        "mma.sync.aligned.m16n8k8.row.col.f32.tf32.tf32.f32 "
        "{%0,%1,%2,%3},{%4,%5,%6,%7},{%8,%9},{%0,%1,%2,%3};"
        : "+f"(d[0]), "+f"(d[1]), "+f"(d[2]), "+f"(d[3])
        : "r"(__float_as_uint(alo.x)), "r"(__float_as_uint(ahi.x)),
          "r"(__float_as_uint(alo.y)), "r"(__float_as_uint(ahi.y)),
          "r"(__float_as_uint(bx)),    "r"(__float_as_uint(by)));
}
__device__ __forceinline__ void mma_tf32_hi(float* d, const float4& alo, const float4& ahi,
                                            float bx, float by) {
    asm volatile(
        "mma.sync.aligned.m16n8k8.row.col.f32.tf32.tf32.f32 "
        "{%0,%1,%2,%3},{%4,%5,%6,%7},{%8,%9},{%0,%1,%2,%3};"
        : "+f"(d[0]), "+f"(d[1]), "+f"(d[2]), "+f"(d[3])
        : "r"(__float_as_uint(alo.z)), "r"(__float_as_uint(ahi.z)),
          "r"(__float_as_uint(alo.w)), "r"(__float_as_uint(ahi.w)),
          "r"(__float_as_uint(bx)),    "r"(__float_as_uint(by)));
}

__device__ __forceinline__ float warp_max(float v) {
    #pragma unroll
    for (int o = 16; o; o >>= 1) v = fmaxf(v, __shfl_xor_sync(0xFFFFFFFFu, v, o));
    return v;
}
__device__ __forceinline__ float warp_sum(float v) {
    #pragma unroll
    for (int o = 16; o; o >>= 1) v += __shfl_xor_sync(0xFFFFFFFFu, v, o);
    return v;
}

// digit-swap permutation within each 16-element block (involution)
__device__ __forceinline__ int perm16(int j) {
    return (j & ~15) | ((j & 3) << 2) | ((j >> 2) & 3);
}

// ---------------------------------------------------------------------------
// Round to tf32 + permute each 16-float block (4x4 in-block transpose).
// One thread per 16-float block, grid-stride.
// ---------------------------------------------------------------------------
__global__ void __launch_bounds__(256)
roundperm_k(const float* __restrict__ in, float* __restrict__ out, int nblk)
{
    int i = blockIdx.x * blockDim.x + threadIdx.x;
    const int stride = gridDim.x * blockDim.x;
    for (; i < nblk; i += stride) {
        const float4* s = (const float4*)(in + (long)i * 16);
        float4* d = (float4*)(out + (long)i * 16);
        float4 a0 = s[0], a1 = s[1], a2 = s[2], a3 = s[3];
        d[0] = make_float4(roundtf(a0.x), roundtf(a1.x), roundtf(a2.x), roundtf(a3.x));
        d[1] = make_float4(roundtf(a0.y), roundtf(a1.y), roundtf(a2.y), roundtf(a3.y));
        d[2] = make_float4(roundtf(a0.z), roundtf(a1.z), roundtf(a2.z), roundtf(a3.z));
        d[3] = make_float4(roundtf(a0.w), roundtf(a1.w), roundtf(a2.w), roundtf(a3.w));
    }
}

// ---------------------------------------------------------------------------
// Batched 32x32 tile transpose with tf32 round + perm-K output columns.
// out[b][c][perm(r)] = round(in[b][r][c])
// ---------------------------------------------------------------------------
__global__ void __launch_bounds__(256)
transposeperm_k(const float* __restrict__ in, float* __restrict__ out, int R, int Cc)
{
    __shared__ float t[32][33];
    const long bo = (long)blockIdx.z * R * Cc;
    in += bo; out += bo;
    const int r0 = blockIdx.x * 32, c0 = blockIdx.y * 32;
    const int x = threadIdx.x, y = threadIdx.y;   // block (32, 8)
    #pragma unroll
    for (int i = 0; i < 32; i += 8)
        t[y + i][x] = roundtf(in[(long)(r0 + y + i) * Cc + c0 + x]);
    __syncthreads();
    const int px = (x & 16) | ((x & 3) << 2) | ((x >> 2) & 3);
    #pragma unroll
    for (int i = 0; i < 32; i += 8)
        out[(long)(c0 + y + i) * R + r0 + px] = t[x][y + i];
}

// ---------------------------------------------------------------------------
// TF32 mma.sync GEMM on perm-K operands:  C[M,N] = A[M,K] * B[N,K]^T
// CTA tile 64x128, K-chunk 16, 256 threads (8 warps 2x4), warp 32x32.
// Per K16 chunk per warp: 8 LDS.128 + 16 HMMA (zero cvt, zero scalar LDS).
// CAUSAL_SKIP: skip CTAs above diagonal;  KLIMIT: Keff = ceil(m0+64,128)
// PERM_OUT: write C in perm-K layout;     ROUND_OUT: tf32-round outputs
// ---------------------------------------------------------------------------
template <bool CAUSAL_SKIP, bool KLIMIT, bool PERM_OUT, bool ROUND_OUT>
__global__ void __launch_bounds__(256, 2)
mma_gemm(const float* __restrict__ A, const float* __restrict__ Bm,
         float* __restrict__ C,
         int K, int lda, int ldb, int ldc, long sA, long sB, long sC)
{
    const int m0 = blockIdx.y * 64;
    const int n0 = blockIdx.x * 128;
    if (CAUSAL_SKIP && n0 > m0 + 63) return;

    A  += (long)blockIdx.z * sA;
    Bm += (long)blockIdx.z * sB;
    C  += (long)blockIdx.z * sC;

    const int Keff = KLIMIT ? min(K, (m0 + 64 + 127) & ~127) : K;
    const int nkt  = Keff >> 4;

    __shared__ __align__(16) float As[2][64 * 16];
    __shared__ __align__(16) float Bs[2][128 * 16];

    const int tid  = threadIdx.x;
    const int warp = tid >> 5;
    const int lane = tid & 31;
    const int wm   = warp >> 2;     // 0..1
    const int wn   = warp & 3;      // 0..3
    const int q    = lane & 3;
    const int lg   = lane >> 2;

    auto load_stage = [&](int st, int kt) {
        const int k0 = kt << 4;
        {   // A: 64x16 = 256 16B chunks, 1/thread
            const int r = tid >> 2, g = tid & 3;
            cp16(&As[st][r * 16 + g * 4], A + (long)(m0 + r) * lda + k0 + g * 4);
        }
        #pragma unroll
        for (int i = 0; i < 2; i++) {   // B: 128x16 = 512 chunks, 2/thread
            const int c = tid + (i << 8);
            const int r = c >> 2, g = c & 3;
            cp16(&Bs[st][r * 16 + g * 4], Bm + (long)(n0 + r) * ldb + k0 + g * 4);
        }
        asm volatile("cp.async.commit_group;\n");
    };

    float acc[2][4][4] = {};

    load_stage(0, 0);
    for (int kt = 0; kt < nkt; ++kt) {
        const int cur = kt & 1;
        if (kt + 1 < nkt) { load_stage(cur ^ 1, kt + 1);
                            asm volatile("cp.async.wait_group 1;\n"); }
        else              { asm volatile("cp.async.wait_group 0;\n"); }
        __syncthreads();

        const float4* Af = (const float4*)As[cur];
        const float4* Bf = (const float4*)Bs[cur];

        float4 alo[2], ahi[2], bv[4];
        #pragma unroll
        for (int mi = 0; mi < 2; mi++) {
            const int row = wm * 32 + mi * 16 + lg;
            alo[mi] = Af[row * 4 + q];
            ahi[mi] = Af[(row + 8) * 4 + q];
        }
        #pragma unroll
        for (int ni = 0; ni < 4; ni++) {
            const int nb = wn * 32 + ni * 8 + lg;
            bv[ni] = Bf[nb * 4 + q];
        }
        #pragma unroll
        for (int mi = 0; mi < 2; mi++)
            #pragma unroll
            for (int ni = 0; ni < 4; ni++) {
                mma_tf32   (acc[mi][ni], alo[mi], ahi[mi], bv[ni].x, bv[ni].y);
                mma_tf32_hi(acc[mi][ni], alo[mi], ahi[mi], bv[ni].z, bv[ni].w);
            }
        __syncthreads();
    }

    // Epilogue
    #pragma unroll
    for (int mi = 0; mi < 2; mi++) {
        #pragma unroll
        for (int ni = 0; ni < 4; ni++) {
            const int r0 = m0 + wm * 32 + mi * 16 + lg;
            const int c0 = n0 + wn * 32 + ni * 8 + 2 * q;
            float v0 = acc[mi][ni][0], v1 = acc[mi][ni][1];
            float v2 = acc[mi][ni][2], v3 = acc[mi][ni][3];
            if (ROUND_OUT) { v0 = roundtf(v0); v1 = roundtf(v1);
                             v2 = roundtf(v2); v3 = roundtf(v3); }
            if (PERM_OUT) {
                const int p0 = perm16(c0), p1 = perm16(c0 + 1);
                C[(long)r0 * ldc + p0]       = v0;
                C[(long)r0 * ldc + p1]       = v1;
                C[(long)(r0 + 8) * ldc + p0] = v2;
                C[(long)(r0 + 8) * ldc + p1] = v3;
            } else {
                *(float2*)&C[(long)r0 * ldc + c0]       = make_float2(v0, v1);
                *(float2*)&C[(long)(r0 + 8) * ldc + c0] = make_float2(v2, v3);
            }
        }
    }
}

// ---------------------------------------------------------------------------
// In-place causal row softmax on perm-K P, logits s/32, tf32-rounded output.
// Physical index jp maps to logical column perm16(jp) for the causal mask.
// Zero-fills [len, lenPad) (exp(-inf)=0); PV never reads past lenPad.
// ---------------------------------------------------------------------------
__global__ void __launch_bounds__(256)
softmax_k(float* __restrict__ P)
{
    const int row = blockIdx.x;
    const int b = row >> 11;
    const int i = row & 2047;
    float* p = P + ((long)b * Sq + i) * Sq;
    const int tid = threadIdx.x;
    const int len = i + 1;
    const int lenPad = (len + 127) & ~127;

    float v[8];
    int cnt = 0;
    for (int jp = tid; jp < lenPad; jp += 256) {
        const float raw = p[jp];
        v[cnt++] = (perm16(jp) < len) ? raw : -3.4e38f;
    }

    float mx = -3.4e38f;
    #pragma unroll
    for (int c = 0; c < 8; c++) if (c < cnt) mx = fmaxf(mx, v[c]);
    mx = warp_max(mx);

    __shared__ float red[8];
    if ((tid & 31) == 0) red[tid >> 5] = mx;
    __syncthreads();
    mx = red[0];
    #pragma unroll
    for (int w = 1; w < 8; w++) mx = fmaxf(mx, red[w]);

    float s = 0.f;
    #pragma unroll
    for (int c = 0; c < 8; c++) {
        if (c < cnt) { v[c] = __expf((v[c] - mx) * 0.03125f); s += v[c]; }
    }
    s = warp_sum(s);
    __syncthreads();
    if ((tid & 31) == 0) red[tid >> 5] = s;
    __syncthreads();
    float tot = 0.f;
    #pragma unroll
    for (int w = 0; w < 8; w++) tot += red[w];
    const float inv = 1.0f / tot;

    cnt = 0;
    for (int jp = tid; jp < lenPad; jp += 256)
        p[jp] = roundtf(v[cnt++] * inv);
}

// ---------------------------------------------------------------------------
extern "C" void kernel_launch(void* const* d_in, const int* in_sizes, int n_in,
                              void* d_out, int out_size)
{
    const float* x  = (const float*)d_in[0];
    const float* Wq = (const float*)d_in[1];
    const float* Wk = (const float*)d_in[2];
    const float* Wv = (const float*)d_in[3];
    float* out = (float*)d_out;

    float *X, *WqT, *WkT, *WvT, *Q, *K, *V, *Vt, *P;
    cudaGetSymbolAddress((void**)&X,   g_X);
    cudaGetSymbolAddress((void**)&WqT, g_WqT);
    cudaGetSymbolAddress((void**)&WkT, g_WkT);
    cudaGetSymbolAddress((void**)&WvT, g_WvT);
    cudaGetSymbolAddress((void**)&Q,   g_Q);
    cudaGetSymbolAddress((void**)&K,   g_K);
    cudaGetSymbolAddress((void**)&V,   g_V);
    cudaGetSymbolAddress((void**)&Vt,  g_Vt);
    cudaGetSymbolAddress((void**)&P,   g_P);

    // 0) round+perm x; round+transpose+perm weights
    roundperm_k<<<1024, 256>>>(x, X, (Bsz * Sq * Dm) / 16);
    {
        dim3 tb(32, 8);
        dim3 gw(Dm / 32, Dm / 32, 1);
        transposeperm_k<<<gw, tb>>>(Wq, WqT, Dm, Dm);
        transposeperm_k<<<gw, tb>>>(Wk, WkT, Dm, Dm);
        transposeperm_k<<<gw, tb>>>(Wv, WvT, Dm, Dm);
    }

    const int M = Bsz * Sq;   // 8192

    // 1) Projections (NT vs transposed weights)
    {
        dim3 grid(Dm / 128, M / 64, 1);
        mma_gemm<false, false, true,  true ><<<grid, 256>>>(X, WqT, Q, Dm, Dm, Dm, Dm, 0, 0, 0);
        mma_gemm<false, false, true,  true ><<<grid, 256>>>(X, WkT, K, Dm, Dm, Dm, Dm, 0, 0, 0);
        mma_gemm<false, false, false, false><<<grid, 256>>>(X, WvT, V, Dm, Dm, Dm, Dm, 0, 0, 0);
    }

    // 2) Scores: S_b = Q_b K_b^T (causal-skip), perm-K output (no round)
    {
        dim3 grid(Sq / 128, Sq / 64, Bsz);
        mma_gemm<true, false, true, false><<<grid, 256>>>(
            Q, K, P, Dm, Dm, Dm, Sq,
            (long)Sq * Dm, (long)Sq * Dm, (long)Sq * Sq);
    }

    // 3) Softmax (in place, causal via perm mapping, tf32-rounded probs)
    softmax_k<<<Bsz * Sq, 256>>>(P);

    // 4) V^T (round+perm), then O = P Vt^T (causal K-limit), normal output
    {
        dim3 tb(32, 8);
        transposeperm_k<<<dim3(Sq / 32, Dm / 32, Bsz), tb>>>(V, Vt, Sq, Dm);
        dim3 grid(Dm / 128, Sq / 64, Bsz);
        mma_gemm<false, true, false, false><<<grid, 256>>>(
            P, Vt, out, Sq, Sq, Sq, Dm,
            (long)Sq * Sq, (long)Sq * Dm, (long)Sq * Dm);
    }

    (void)in_sizes; (void)n_in; (void)out_size;
}